// round 4
// baseline (speedup 1.0000x reference)
#include <cuda_runtime.h>
#include <cstddef>

// Problem constants (fixed by the dataset problem)
#define CC 32
#define HH 128
#define WW 512
#define PAD 40
#define DD (PAD + 1)

// out[c,d,h,w] = in1[c,h,w] * (w >= d ? in2[c,h,w-d] : 0)
//
// One CTA per (c,h) row (4096 CTAs, 128 threads). The in2 row is staged once
// into shared memory with a PAD-float zero apron. Each thread owns an aligned
// float4 of the row; across the fully-unrolled d-loop the in2 window slides
// left one float per disparity, kept in 4 rotating registers with one scalar
// LDS per iteration. Stores are fire-and-forget STG.128 (evict-first).
//
// __launch_bounds__(128, 16) caps registers at 32 so 16 CTAs (64 warps) fit
// per SM -> 100% theoretical occupancy, maximizing outstanding stores for the
// HBM write stream (the binding resource).
__global__ __launch_bounds__(128, 16) void corr1d_row_kernel(
    const float* __restrict__ in1,
    const float* __restrict__ in2,
    float* __restrict__ out)
{
    __shared__ float s2[PAD + WW];   // 552 floats; [0,PAD) is the zero apron

    const int row = blockIdx.x;      // (c,h) in [0, C*H)
    const int t   = threadIdx.x;     // 0..127
    const int c   = row / HH;
    const int h   = row % HH;

    // Stage rows (read-once: evict-first loads keep L2 free for writes).
    // PAD*4 = 160 bytes, 16B-aligned, so float4 stores into s2+PAD are legal.
    const float4 a =
        __ldcs(reinterpret_cast<const float4*>(in1 + (size_t)row * WW) + t);
    if (t < PAD) s2[t] = 0.0f;
    reinterpret_cast<float4*>(s2 + PAD)[t] =
        __ldcs(reinterpret_cast<const float4*>(in2 + (size_t)row * WW) + t);
    __syncthreads();

    // Output base for d=0 plane of this (c,h) row; planes are HH*WW apart.
    float4* po = reinterpret_cast<float4*>(
        out + ((size_t)(c * DD) * HH + h) * WW) + t;
    const size_t plane_stride_v4 = (size_t)HH * WW / 4;   // 16384 float4s

    // d=0 window: one aligned LDS.128.
    float4 b = reinterpret_cast<const float4*>(s2 + PAD)[t];
    float b0 = b.x, b1 = b.y, b2 = b.z, b3 = b.w;

    const int base = PAD + 4 * t;    // s2 index of b0 at d=0

    #pragma unroll
    for (int d = 0; d <= PAD; ++d) {
        float4 r;
        r.x = a.x * b0;
        r.y = a.y * b1;
        r.z = a.z * b2;
        r.w = a.w * b3;
        __stcs(po + (size_t)d * plane_stride_v4, r);

        // Slide the window left by one for the next disparity.
        if (d < PAD) {
            b3 = b2;
            b2 = b1;
            b1 = b0;
            b0 = s2[base - d - 1];
        }
    }
}

extern "C" void kernel_launch(void* const* d_in, const int* in_sizes, int n_in,
                              void* d_out, int out_size)
{
    const float* in1 = (const float*)d_in[0];
    const float* in2 = (const float*)d_in[1];
    float* out = (float*)d_out;

    corr1d_row_kernel<<<CC * HH, WW / 4>>>(in1, in2, out);
}

// round 5
// speedup vs baseline: 1.3466x; 1.3466x over previous
#include <cuda_runtime.h>
#include <cstddef>

// Problem constants (fixed by the dataset problem)
#define CC 32
#define HH 128
#define WW 512
#define PAD 40
#define DD (PAD + 1)

// out[c,d,h,w] = in1[c,h,w] * (w >= d ? in2[c,h,w-d] : 0)
//
// One CTA per (c,h) row (4096 CTAs, 128 threads). The in2 row is staged once
// into shared memory with a PAD-float zero apron. Thread t owns the aligned
// float4 at w = 4t. Across the fully-unrolled d-loop the needed in2 window
// slides left one float per disparity; instead of re-reading shared memory
// (stride-4 lanes -> 4-way bank conflict -> 4 extra L1tex wavefronts/iter,
// which contended with the store stream), the slide is done through the
// shuffle network: thread t's next b0 is thread t-1's current b3. Only lane 0
// of each warp reads shared (conflict-free, 1 lane). In-loop L1tex traffic is
// stores-only.
__global__ __launch_bounds__(128) void corr1d_row_kernel(
    const float* __restrict__ in1,
    const float* __restrict__ in2,
    float* __restrict__ out)
{
    __shared__ float s2[PAD + WW];   // 552 floats; [0,PAD) is the zero apron

    const int row  = blockIdx.x;     // (c,h) in [0, C*H)
    const int t    = threadIdx.x;    // 0..127
    const int lane = t & 31;
    const int c    = row / HH;
    const int h    = row % HH;

    // Stage rows. PAD*4 = 160 bytes, 16B-aligned, so float4 stores into
    // s2+PAD are legal.
    const float4 a = reinterpret_cast<const float4*>(in1 + (size_t)row * WW)[t];
    if (t < PAD) s2[t] = 0.0f;
    reinterpret_cast<float4*>(s2 + PAD)[t] =
        reinterpret_cast<const float4*>(in2 + (size_t)row * WW)[t];
    __syncthreads();

    // Output base for d=0 plane of this (c,h) row; planes are HH*WW apart.
    float4* po = reinterpret_cast<float4*>(
        out + ((size_t)(c * DD) * HH + h) * WW) + t;
    const size_t plane_stride_v4 = (size_t)HH * WW / 4;   // 16384 float4s

    // d=0 window: one aligned LDS.128.
    float4 b = reinterpret_cast<const float4*>(s2 + PAD)[t];
    float b0 = b.x, b1 = b.y, b2 = b.z, b3 = b.w;

    const int base = PAD + 4 * t;    // s2 index of b0 at d=0

    #pragma unroll
    for (int d = 0; d <= PAD; ++d) {
        float4 r;
        r.x = a.x * b0;
        r.y = a.y * b1;
        r.z = a.z * b2;
        r.w = a.w * b3;
        __stcs(po + (size_t)d * plane_stride_v4, r);   // streaming store

        if (d < PAD) {
            // Next b0 = s2[base - d - 1] = previous lane's current b3.
            float carry = __shfl_up_sync(0xffffffffu, b3, 1);
            if (lane == 0) carry = s2[base - d - 1];   // warp-boundary fill
            b3 = b2;
            b2 = b1;
            b1 = b0;
            b0 = carry;
        }
    }
}

extern "C" void kernel_launch(void* const* d_in, const int* in_sizes, int n_in,
                              void* d_out, int out_size)
{
    const float* in1 = (const float*)d_in[0];
    const float* in2 = (const float*)d_in[1];
    float* out = (float*)d_out;

    corr1d_row_kernel<<<CC * HH, WW / 4>>>(in1, in2, out);
}